// round 6
// baseline (speedup 1.0000x reference)
#include <cuda_runtime.h>
#include <cuda_bf16.h>

#define SENSOR   256
#define IMG_W    1024
#define IMG_H    1024
#define SPP      16
#define NCH      3
#define NBATCH   4
#define HW       (IMG_H * IMG_W)

__device__ __forceinline__ float ftanh(float x) {
    float e = __expf(2.0f * x);
    return 1.0f - __fdividef(2.0f, e + 1.0f);
}

__global__ __launch_bounds__(128, 8)
void foveated_sensor_kernel(const float* __restrict__ img,
                            const float* __restrict__ t,
                            const float* __restrict__ jitter,
                            float* __restrict__ out)
{
    const int p  = blockIdx.x * 128 + threadIdx.x;   // sensor pixel 0..65535
    const int b0 = blockIdx.y * 2;                    // batch pair: 0 or 2
    const int sw = p & (SENSOR - 1);
    const int sh = p >> 8;

    const float step = 2.0f / (float)SENSOR;
    const float pxv = -1.0f + (float)sw * step;
    const float pyv = -1.0f + (float)sh * step;

    const float tt    = __ldg(t);
    const float s     = tanhf(tt);
    const float inv_s = 1.0f / s;

    const float* __restrict__ pA = img + (size_t)b0 * NCH * HW;        // batch b0, ch0
    const float* __restrict__ pB = pA + HW;                            // b0 ch1
    const float* __restrict__ pC = pA + 2 * HW;                        // b0 ch2
    const float* __restrict__ pD = pA + 3 * HW;                        // b0+1 ch0
    const float* __restrict__ pE = pA + 4 * HW;                        // b0+1 ch1
    const float* __restrict__ pF = pA + 5 * HW;                        // b0+1 ch2

    const float2* __restrict__ jit = (const float2*)jitter;

    float accA = 0.f, accB = 0.f, accC = 0.f;
    float accD = 0.f, accE = 0.f, accF = 0.f;
    float dsum = 0.f;

#pragma unroll 2
    for (int k = 0; k < SPP; ++k) {
        float2 j = __ldg(&jit[(k << 16) + p]);
        float posx = pxv + j.x * step;
        float posy = pyv + j.y * step;

        float thx = ftanh(tt * posx);
        float thy = ftanh(tt * posy);

        float ddx = tt * (1.0f - thx * thx) * inv_s;
        float ddy = tt * (1.0f - thy * thy) * inv_s;
        float det = ddx * ddy;
        dsum += det;

        float gx = (thx * inv_s + 1.0f) * (0.5f * IMG_W) - 0.5f;
        float gy = (thy * inv_s + 1.0f) * (0.5f * IMG_H) - 0.5f;
        gx = fminf(fmaxf(gx, 0.0f), (float)(IMG_W - 1));
        gy = fminf(fmaxf(gy, 0.0f), (float)(IMG_H - 1));

        float x0f = floorf(gx);
        float y0f = floorf(gy);
        float wx = gx - x0f;
        float wy = gy - y0f;

        int x0 = (int)x0f;
        int y0 = (int)y0f;
        int x1 = min(x0 + 1, IMG_W - 1);
        int y1 = min(y0 + 1, IMG_H - 1);

        const int o00 = (y0 << 10) + x0;
        const int o01 = (y0 << 10) + x1;
        const int o10 = (y1 << 10) + x0;
        const int o11 = (y1 << 10) + x1;

        float a00 = __ldg(pA + o00), a01 = __ldg(pA + o01), a10 = __ldg(pA + o10), a11 = __ldg(pA + o11);
        float b00 = __ldg(pB + o00), b01 = __ldg(pB + o01), b10 = __ldg(pB + o10), b11 = __ldg(pB + o11);
        float c00 = __ldg(pC + o00), c01 = __ldg(pC + o01), c10 = __ldg(pC + o10), c11 = __ldg(pC + o11);
        float d00 = __ldg(pD + o00), d01 = __ldg(pD + o01), d10 = __ldg(pD + o10), d11 = __ldg(pD + o11);
        float e00 = __ldg(pE + o00), e01 = __ldg(pE + o01), e10 = __ldg(pE + o10), e11 = __ldg(pE + o11);
        float f00 = __ldg(pF + o00), f01 = __ldg(pF + o01), f10 = __ldg(pF + o10), f11 = __ldg(pF + o11);

        float top, bot;
        top = fmaf(wx, a01 - a00, a00); bot = fmaf(wx, a11 - a10, a10);
        accA = fmaf(fmaf(wy, bot - top, top), det, accA);
        top = fmaf(wx, b01 - b00, b00); bot = fmaf(wx, b11 - b10, b10);
        accB = fmaf(fmaf(wy, bot - top, top), det, accB);
        top = fmaf(wx, c01 - c00, c00); bot = fmaf(wx, c11 - c10, c10);
        accC = fmaf(fmaf(wy, bot - top, top), det, accC);
        top = fmaf(wx, d01 - d00, d00); bot = fmaf(wx, d11 - d10, d10);
        accD = fmaf(fmaf(wy, bot - top, top), det, accD);
        top = fmaf(wx, e01 - e00, e00); bot = fmaf(wx, e11 - e10, e10);
        accE = fmaf(fmaf(wy, bot - top, top), det, accE);
        top = fmaf(wx, f01 - f00, f00); bot = fmaf(wx, f11 - f10, f10);
        accF = fmaf(fmaf(wy, bot - top, top), det, accF);
    }

    const float invd = 1.0f / dsum;
    const int obase = (b0 * NCH) << 16;
    out[obase + (0 << 16) + p] = accA * invd;
    out[obase + (1 << 16) + p] = accB * invd;
    out[obase + (2 << 16) + p] = accC * invd;
    out[obase + (3 << 16) + p] = accD * invd;
    out[obase + (4 << 16) + p] = accE * invd;
    out[obase + (5 << 16) + p] = accF * invd;
}

extern "C" void kernel_launch(void* const* d_in, const int* in_sizes, int n_in,
                              void* d_out, int out_size)
{
    const float* img    = (const float*)d_in[0];
    const float* t      = (const float*)d_in[1];
    const float* jitter = (const float*)d_in[2];
    float* out          = (float*)d_out;

    dim3 grid(SENSOR * SENSOR / 128, NBATCH / 2);
    foveated_sensor_kernel<<<grid, 128>>>(img, t, jitter, out);
}

// round 7
// speedup vs baseline: 1.1472x; 1.1472x over previous
#include <cuda_runtime.h>
#include <cuda_bf16.h>

#define SENSOR   256
#define IMG_W    1024
#define IMG_H    1024
#define SPP      16
#define NCH      3
#define NBATCH   4
#define HW       (IMG_H * IMG_W)

__device__ __forceinline__ float ftanh(float x) {
    float e = __expf(2.0f * x);
    return 1.0f - __fdividef(2.0f, e + 1.0f);
}

__global__ __launch_bounds__(128, 10)
void foveated_sensor_kernel(const float* __restrict__ img,
                            const float* __restrict__ t,
                            const float* __restrict__ jitter,
                            float* __restrict__ out)
{
    const int p  = blockIdx.x * 128 + threadIdx.x;   // sensor pixel 0..65535
    const int b  = blockIdx.y;                        // batch 0..3
    const int sw = p & (SENSOR - 1);
    const int sh = p >> 8;

    const float step = 2.0f / (float)SENSOR;
    const float pxv = -1.0f + (float)sw * step;
    const float pyv = -1.0f + (float)sh * step;

    const float tt    = __ldg(t);
    const float s     = tanhf(tt);
    const float inv_s = 1.0f / s;

    const float* __restrict__ imgb = img + (size_t)b * NCH * HW;
    const float2* __restrict__ jit = (const float2*)jitter;

    float acc0 = 0.f, acc1 = 0.f, acc2 = 0.f, dsum = 0.f;

#pragma unroll 4
    for (int k = 0; k < SPP; ++k) {
        float2 j = __ldg(&jit[(k << 16) + p]);
        float posx = pxv + j.x * step;
        float posy = pyv + j.y * step;

        float thx = ftanh(tt * posx);
        float thy = ftanh(tt * posy);

        float ddx = tt * (1.0f - thx * thx) * inv_s;
        float ddy = tt * (1.0f - thy * thy) * inv_s;
        float det = ddx * ddy;
        dsum += det;

        float gx = (thx * inv_s + 1.0f) * (0.5f * IMG_W) - 0.5f;
        float gy = (thy * inv_s + 1.0f) * (0.5f * IMG_H) - 0.5f;
        gx = fminf(fmaxf(gx, 0.0f), (float)(IMG_W - 1));
        gy = fminf(fmaxf(gy, 0.0f), (float)(IMG_H - 1));

        float x0f = floorf(gx);
        float y0f = floorf(gy);
        float wx = gx - x0f;
        float wy = gy - y0f;

        int x0 = (int)x0f;
        int y0 = (int)y0f;
        int x1 = min(x0 + 1, IMG_W - 1);
        int y1 = min(y0 + 1, IMG_H - 1);

        const int o00 = (y0 << 10) + x0;
        const int o01 = (y0 << 10) + x1;
        const int o10 = (y1 << 10) + x0;
        const int o11 = (y1 << 10) + x1;

        // channel 0
        float a00 = __ldg(imgb + o00);
        float a01 = __ldg(imgb + o01);
        float a10 = __ldg(imgb + o10);
        float a11 = __ldg(imgb + o11);
        // channel 1
        const float* ip1 = imgb + HW;
        float b00 = __ldg(ip1 + o00);
        float b01 = __ldg(ip1 + o01);
        float b10 = __ldg(ip1 + o10);
        float b11 = __ldg(ip1 + o11);
        // channel 2
        const float* ip2 = imgb + 2 * HW;
        float c00 = __ldg(ip2 + o00);
        float c01 = __ldg(ip2 + o01);
        float c10 = __ldg(ip2 + o10);
        float c11 = __ldg(ip2 + o11);

        float topa = fmaf(wx, a01 - a00, a00);
        float bota = fmaf(wx, a11 - a10, a10);
        acc0 = fmaf(fmaf(wy, bota - topa, topa), det, acc0);

        float topb = fmaf(wx, b01 - b00, b00);
        float botb = fmaf(wx, b11 - b10, b10);
        acc1 = fmaf(fmaf(wy, botb - topb, topb), det, acc1);

        float topc = fmaf(wx, c01 - c00, c00);
        float botc = fmaf(wx, c11 - c10, c10);
        acc2 = fmaf(fmaf(wy, botc - topc, topc), det, acc2);
    }

    const float invd = 1.0f / dsum;
    out[((b * NCH + 0) << 16) + p] = acc0 * invd;
    out[((b * NCH + 1) << 16) + p] = acc1 * invd;
    out[((b * NCH + 2) << 16) + p] = acc2 * invd;
}

extern "C" void kernel_launch(void* const* d_in, const int* in_sizes, int n_in,
                              void* d_out, int out_size)
{
    const float* img    = (const float*)d_in[0];
    const float* t      = (const float*)d_in[1];
    const float* jitter = (const float*)d_in[2];
    float* out          = (float*)d_out;

    dim3 grid(SENSOR * SENSOR / 128, NBATCH);
    foveated_sensor_kernel<<<grid, 128>>>(img, t, jitter, out);
}